// round 3
// baseline (speedup 1.0000x reference)
#include <cuda_runtime.h>
#include <cstdint>

// Problem constants
constexpr int BATCH = 2, SEQ = 2048, DMODEL = 4096;
constexpr int NH = 32, NKV = 8, HD = 128;
constexpr int MROWS = BATCH * SEQ;                 // 4096
constexpr float ATT_SCALE = 0.08838834764831845f; // 128^-0.5

// Scratch: gmem images already in fragment-permuted + swizzled smem layout.
// g_q : [b][h][qt(16)]  tile 128 rows x 128 w
// g_k : [b][hk][kt(32)] tile  64 rows x 128 w
// g_vt: [b][hk][kt(32)] tile 128 rows(d) x 64 w(s)
__device__ float g_q [(size_t)BATCH * NH  * 16 * 16384];
__device__ float g_k [(size_t)BATCH * NKV * 32 * 8192];
__device__ float g_vt[(size_t)BATCH * NKV * 32 * 8192];
__device__ float g_ao[(size_t)MROWS * DMODEL];     // attention output, token-major

__device__ __forceinline__ float tf32r(float x) {
    uint32_t u;
    asm("cvt.rna.tf32.f32 %0, %1;" : "=r"(u) : "f"(x));
    return __uint_as_float(u);
}

// in-row fragment permutation: k -> (k&~7) | ((k&3)<<1) | ((k>>2)&1)
__device__ __forceinline__ int qperm(int k) {
    return (k & ~7) | ((k & 3) << 1) | ((k >> 2) & 1);
}

__device__ __forceinline__ void mma8(float* c, const uint32_t* a, const uint32_t* b) {
    asm volatile(
        "mma.sync.aligned.m16n8k8.row.col.f32.tf32.tf32.f32 "
        "{%0,%1,%2,%3}, {%4,%5,%6,%7}, {%8,%9}, {%0,%1,%2,%3};"
        : "+f"(c[0]), "+f"(c[1]), "+f"(c[2]), "+f"(c[3])
        : "r"(a[0]), "r"(a[1]), "r"(a[2]), "r"(a[3]), "r"(b[0]), "r"(b[1]));
}

__device__ __forceinline__ void cpa16(float* s, const float* g) {
    uint32_t sa = (uint32_t)__cvta_generic_to_shared(s);
    asm volatile("cp.async.cg.shared.global [%0], [%1], 16;\n" :: "r"(sa), "l"(g));
}
#define CP_COMMIT() asm volatile("cp.async.commit_group;\n" ::: "memory")
#define CP_WAIT0()  asm volatile("cp.async.wait_group 0;\n" ::: "memory")

// ---------------------------------------------------------------------------
// GEMM: C[4096, N] = A[4096,4096] @ W^T. MODE 0: QKV + RoPE, packed scatter.
// MODE 1: out-proj, plain epilogue. BM=128,BN=128,BK=32; 256 thr, 8 warps.
// smem tiles use permuted+swizzled layout -> all MMA operand loads are LDS.64.
// ---------------------------------------------------------------------------
template <int MODE>
__global__ void __launch_bounds__(256, 1)
gemm_tf32(const float* __restrict__ A,
          const float* __restrict__ W0,
          const float* __restrict__ W1,
          const float* __restrict__ W2,
          const float* __restrict__ cosp,
          const float* __restrict__ sinp,
          float* __restrict__ Cout)
{
    extern __shared__ float smf[];
    float* As = smf;          // 2 * 4096 floats
    float* Bs = smf + 8192;   // 2 * 4096 floats

    const int tid = threadIdx.x;
    const int bn = blockIdx.x, bm = blockIdx.y;
    const int m0 = bm * 128;

    const float* Ap = (MODE == 1) ? g_ao : A;

    const float* W;
    int nbase, btype = 0, hidx = 0;
    if (MODE == 0) {
        if (bn < 32)      { W = W0; nbase = bn * 128;        btype = 0; hidx = bn; }
        else if (bn < 40) { W = W1; nbase = (bn - 32) * 128; btype = 1; hidx = bn - 32; }
        else              { W = W2; nbase = (bn - 40) * 128; btype = 2; hidx = bn - 40; }
    } else {
        W = W0; nbase = bn * 128;
    }

    float4 ra[4], rb[4];
    auto loadg = [&](int kt) {
        const int k0 = kt * 32;
#pragma unroll
        for (int i = 0; i < 4; i++) {
            int f = tid + i * 256;
            int row = f >> 3, c4 = (f & 7) * 4;
            ra[i] = *(const float4*)(Ap + (size_t)(m0 + row) * 4096 + k0 + c4);
            rb[i] = *(const float4*)(W  + (size_t)(nbase + row) * 4096 + k0 + c4);
        }
    };
    auto stores = [&](int buf) {
#pragma unroll
        for (int i = 0; i < 4; i++) {
            int f = tid + i * 256;
            int row = f >> 3, c4 = (f & 7) * 4;
            int kg = c4 >> 3, cbit = (c4 >> 2) & 1;
            int w0 = kg * 8 + cbit;
            int sx = (row & 3) << 3;
            float* Ab = As + buf * 4096 + row * 32;
            float* Bb = Bs + buf * 4096 + row * 32;
            Ab[(w0 + 0) ^ sx] = tf32r(ra[i].x);
            Ab[(w0 + 2) ^ sx] = tf32r(ra[i].y);
            Ab[(w0 + 4) ^ sx] = tf32r(ra[i].z);
            Ab[(w0 + 6) ^ sx] = tf32r(ra[i].w);
            Bb[(w0 + 0) ^ sx] = tf32r(rb[i].x);
            Bb[(w0 + 2) ^ sx] = tf32r(rb[i].y);
            Bb[(w0 + 4) ^ sx] = tf32r(rb[i].z);
            Bb[(w0 + 6) ^ sx] = tf32r(rb[i].w);
        }
    };

    const int lane = tid & 31, wid = tid >> 5;
    const int gi = lane >> 2, ti = lane & 3;
    const int wm = wid >> 1, wn = wid & 1;
    const int sx = (gi & 3) << 3;

    float acc[2][8][4];
#pragma unroll
    for (int a = 0; a < 2; a++)
#pragma unroll
        for (int b2 = 0; b2 < 8; b2++)
#pragma unroll
            for (int c = 0; c < 4; c++) acc[a][b2][c] = 0.f;

    const int NK = 128;
    loadg(0);
    stores(0);
    for (int kt = 0; kt < NK; kt++) {
        if (kt + 1 < NK) loadg(kt + 1);
        __syncthreads();
        if (kt + 1 < NK) stores((kt + 1) & 1);
        const float* Ab = As + (kt & 1) * 4096;
        const float* Bb = Bs + (kt & 1) * 4096;
#pragma unroll
        for (int kg = 0; kg < 4; kg++) {
            const int kb = kg * 8 + ti * 2;
            uint32_t af[2][4];
#pragma unroll
            for (int mt = 0; mt < 2; mt++) {
                int r = wm * 32 + mt * 16 + gi;
                float2 a0 = *(const float2*)(Ab + r * 32 + (kb ^ sx));
                float2 a1 = *(const float2*)(Ab + (r + 8) * 32 + (kb ^ sx));
                af[mt][0] = __float_as_uint(a0.x);
                af[mt][1] = __float_as_uint(a1.x);
                af[mt][2] = __float_as_uint(a0.y);
                af[mt][3] = __float_as_uint(a1.y);
            }
#pragma unroll
            for (int nt = 0; nt < 8; nt++) {
                int n = wn * 64 + nt * 8 + gi;
                float2 bv = *(const float2*)(Bb + n * 32 + (kb ^ sx));
                uint32_t bf[2] = { __float_as_uint(bv.x), __float_as_uint(bv.y) };
                mma8(acc[0][nt], af[0], bf);
                mma8(acc[1][nt], af[1], bf);
            }
        }
    }
    __syncthreads();

    if (MODE == 1) {
#pragma unroll
        for (int mt = 0; mt < 2; mt++)
#pragma unroll
            for (int nt = 0; nt < 8; nt++) {
                int r = m0 + wm * 32 + mt * 16 + gi;
                int c = bn * 128 + wn * 64 + nt * 8 + 2 * ti;
                *(float2*)(Cout + (size_t)r * 4096 + c) =
                    make_float2(acc[mt][nt][0], acc[mt][nt][1]);
                *(float2*)(Cout + (size_t)(r + 8) * 4096 + c) =
                    make_float2(acc[mt][nt][2], acc[mt][nt][3]);
            }
        return;
    }

    // MODE 0 epilogue: stage tile (swizzled 128x128), then RoPE + packed scatter
    float* Csh = smf; // 16384 floats
#pragma unroll
    for (int mt = 0; mt < 2; mt++)
#pragma unroll
        for (int nt = 0; nt < 8; nt++) {
            int r = wm * 32 + mt * 16 + gi, c = wn * 64 + nt * 8 + 2 * ti;
            Csh[r * 128 + (c ^ sx)]             = acc[mt][nt][0];
            Csh[r * 128 + ((c + 1) ^ sx)]       = acc[mt][nt][1];
            Csh[(r + 8) * 128 + (c ^ sx)]       = acc[mt][nt][2];
            Csh[(r + 8) * 128 + ((c + 1) ^ sx)] = acc[mt][nt][3];
        }
    __syncthreads();

    const int bb = m0 >> 11;
    if (btype <= 1) {
#pragma unroll 4
        for (int i = 0; i < 64; i++) {
            int f = tid + i * 256;
            int r = f >> 7, d = f & 127;
            int rx = (r & 3) << 3;
            int m = m0 + r, s = m & 2047;
            float val = Csh[r * 128 + (d ^ rx)];
            float oth = Csh[r * 128 + (((d + 64) & 127) ^ rx)];
            float rot = (d < 64) ? -oth : oth;
            float cs = cosp[(size_t)m * HD + d];
            float sn = sinp[(size_t)m * HD + d];
            float ov = val * cs + rot * sn;
            if (btype == 0) {
                int qt = (m0 >> 7) & 15;
                size_t base = (((size_t)bb * NH + hidx) * 16 + qt) * 16384;
                g_q[base + r * 128 + (qperm(d) ^ rx)] = tf32r(ov * ATT_SCALE);
            } else {
                int kt = s >> 6, n = s & 63; // n&3 == r&3
                size_t base = (((size_t)bb * NKV + hidx) * 32 + kt) * 8192;
                g_k[base + n * 128 + (qperm(d) ^ rx)] = tf32r(ov);
            }
        }
    } else {
        // V transposed image: tile rows = d, cols(w) = perm(s_local)
#pragma unroll 4
        for (int i = 0; i < 64; i++) {
            int f = tid + i * 256;
            int sl = f >> 7, d = f & 127;
            int s = (m0 & 2047) + sl;
            int kt = s >> 6;
            float v = Csh[sl * 128 + (d ^ ((sl & 3) << 3))];
            size_t base = (((size_t)bb * NKV + hidx) * 32 + kt) * 8192;
            g_vt[base + d * 64 + (qperm(sl & 63) ^ ((d & 3) << 3))] = tf32r(v);
        }
    }
}

// ---------------------------------------------------------------------------
// Flash attention. gmem tiles are pre-packed smem images -> cp.async copies,
// double-buffered K/V; all MMA operand loads are conflict-free LDS.64.
// ---------------------------------------------------------------------------
__global__ void __launch_bounds__(256, 1) attn_kernel()
{
    extern __shared__ float smf[];
    float* Qs  = smf;            // 16384
    float* Ksb = smf + 16384;    // 2 x 8192
    float* Vsb = smf + 32768;    // 2 x 8192
    float* Ps  = smf + 49152;    // 8192

    const int tid = threadIdx.x, lane = tid & 31, wid = tid >> 5;
    const int gi = lane >> 2, ti = lane & 3;
    const int qt = 15 - blockIdx.x;   // heaviest tiles first
    const int h = blockIdx.y, b = blockIdx.z;
    const int q0 = qt * 128, hk = h >> 2;
    const int sx = (gi & 3) << 3;

    const float* Qg = g_q + (((size_t)b * NH + h) * 16 + qt) * 16384;
    const float* Kg = g_k + ((size_t)b * NKV + hk) * 32 * 8192;
    const float* Vg = g_vt + ((size_t)b * NKV + hk) * 32 * 8192;

    // async: Q + first K/V tile
#pragma unroll
    for (int i = 0; i < 16; i++) { int x = (tid + i * 256) * 4; cpa16(Qs + x, Qg + x); }
#pragma unroll
    for (int i = 0; i < 8; i++)  { int x = (tid + i * 256) * 4; cpa16(Ksb + x, Kg + x); }
#pragma unroll
    for (int i = 0; i < 8; i++)  { int x = (tid + i * 256) * 4; cpa16(Vsb + x, Vg + x); }
    CP_COMMIT();

    float o[16][4];
#pragma unroll
    for (int a = 0; a < 16; a++)
#pragma unroll
        for (int c = 0; c < 4; c++) o[a][c] = 0.f;
    float mrow[2] = {-1e30f, -1e30f};
    float lrow[2] = {0.f, 0.f};

    const int r = wid * 16 + gi;
    const int nkt = 2 * qt + 2;
    for (int kt = 0; kt < nkt; kt++) {
        CP_WAIT0();
        __syncthreads();
        if (kt + 1 < nkt) {
            float* Kd = Ksb + ((kt + 1) & 1) * 8192;
            float* Vd = Vsb + ((kt + 1) & 1) * 8192;
            const float* Kg2 = Kg + (size_t)(kt + 1) * 8192;
            const float* Vg2 = Vg + (size_t)(kt + 1) * 8192;
#pragma unroll
            for (int i = 0; i < 8; i++) { int x = (tid + i * 256) * 4; cpa16(Kd + x, Kg2 + x); }
#pragma unroll
            for (int i = 0; i < 8; i++) { int x = (tid + i * 256) * 4; cpa16(Vd + x, Vg2 + x); }
            CP_COMMIT();
        }
        const float* Kb = Ksb + (kt & 1) * 8192;
        const float* Vb = Vsb + (kt & 1) * 8192;

        // S = Q @ K^T   (scale folded into Q)
        float sacc[8][4];
#pragma unroll
        for (int a = 0; a < 8; a++)
#pragma unroll
            for (int c = 0; c < 4; c++) sacc[a][c] = 0.f;
#pragma unroll 4
        for (int kg = 0; kg < 16; kg++) {
            const int kb = kg * 8 + ti * 2;
            float2 a0 = *(const float2*)(Qs + r * 128 + (kb ^ sx));
            float2 a1 = *(const float2*)(Qs + (r + 8) * 128 + (kb ^ sx));
            uint32_t af[4] = { __float_as_uint(a0.x), __float_as_uint(a1.x),
                               __float_as_uint(a0.y), __float_as_uint(a1.y) };
#pragma unroll
            for (int nt = 0; nt < 8; nt++) {
                int n = nt * 8 + gi;
                float2 bv = *(const float2*)(Kb + n * 128 + (kb ^ sx));
                uint32_t bf[2] = { __float_as_uint(bv.x), __float_as_uint(bv.y) };
                mma8(sacc[nt], af, bf);
            }
        }

        // causal mask
        if (kt * 64 + 63 > q0 + wid * 16) {
#pragma unroll
            for (int nt = 0; nt < 8; nt++)
#pragma unroll
                for (int j = 0; j < 4; j++) {
                    int col = kt * 64 + nt * 8 + 2 * ti + (j & 1);
                    int row = q0 + wid * 16 + gi + (j >> 1) * 8;
                    if (col > row) sacc[nt][j] = -1e30f;
                }
        }

        // online softmax; write P packed
#pragma unroll
        for (int j = 0; j < 2; j++) {
            float mx = -1e30f;
#pragma unroll
            for (int nt = 0; nt < 8; nt++)
                mx = fmaxf(mx, fmaxf(sacc[nt][2 * j], sacc[nt][2 * j + 1]));
            mx = fmaxf(mx, __shfl_xor_sync(0xffffffffu, mx, 1));
            mx = fmaxf(mx, __shfl_xor_sync(0xffffffffu, mx, 2));
            float newm = fmaxf(mrow[j], mx);
            float alpha = __expf(mrow[j] - newm);
            mrow[j] = newm;
            float rs = 0.f;
#pragma unroll
            for (int nt = 0; nt < 8; nt++) {
                float p0 = __expf(sacc[nt][2 * j] - newm);
                float p1 = __expf(sacc[nt][2 * j + 1] - newm);
                sacc[nt][2 * j] = p0; sacc[nt][2 * j + 1] = p1;
                rs += p0 + p1;
            }
            rs += __shfl_xor_sync(0xffffffffu, rs, 1);
            rs += __shfl_xor_sync(0xffffffffu, rs, 2);
            lrow[j] = lrow[j] * alpha + rs;
#pragma unroll
            for (int nt = 0; nt < 16; nt++) {
                o[nt][2 * j] *= alpha; o[nt][2 * j + 1] *= alpha;
            }
            int row = wid * 16 + gi + j * 8;
#pragma unroll
            for (int nt = 0; nt < 8; nt++) {
                int c0 = nt * 8 + 2 * ti;
                Ps[row * 64 + (qperm(c0) ^ sx)]     = tf32r(sacc[nt][2 * j]);
                Ps[row * 64 + (qperm(c0 + 1) ^ sx)] = tf32r(sacc[nt][2 * j + 1]);
            }
        }
        __syncwarp();

        // O += P @ V
#pragma unroll
        for (int kg = 0; kg < 8; kg++) {
            const int kb = kg * 8 + ti * 2;
            float2 a0 = *(const float2*)(Ps + r * 64 + (kb ^ sx));
            float2 a1 = *(const float2*)(Ps + (r + 8) * 64 + (kb ^ sx));
            uint32_t af[4] = { __float_as_uint(a0.x), __float_as_uint(a1.x),
                               __float_as_uint(a0.y), __float_as_uint(a1.y) };
#pragma unroll
            for (int nt = 0; nt < 16; nt++) {
                int n = nt * 8 + gi;
                float2 bv = *(const float2*)(Vb + n * 64 + (kb ^ sx));
                uint32_t bf[2] = { __float_as_uint(bv.x), __float_as_uint(bv.y) };
                mma8(o[nt], af, bf);
            }
        }
    }

    __syncthreads();
    const float inv0 = 1.f / lrow[0], inv1 = 1.f / lrow[1];
#pragma unroll
    for (int nt = 0; nt < 16; nt++) {
        int c = nt * 8 + 2 * ti;
        Qs[r * 128 + (c ^ sx)]             = o[nt][0] * inv0;
        Qs[r * 128 + ((c + 1) ^ sx)]       = o[nt][1] * inv0;
        Qs[(r + 8) * 128 + (c ^ sx)]       = o[nt][2] * inv1;
        Qs[(r + 8) * 128 + ((c + 1) ^ sx)] = o[nt][3] * inv1;
    }
    __syncthreads();
    float* AOg = g_ao + ((size_t)(b * SEQ + q0)) * DMODEL + h * HD;
#pragma unroll 4
    for (int i = 0; i < 64; i++) {
        int f = tid + i * 256;
        int rr = f >> 7, d = f & 127;
        AOg[(size_t)rr * DMODEL + d] = Qs[rr * 128 + (d ^ ((rr & 3) << 3))];
    }
}

// ---------------------------------------------------------------------------
extern "C" void kernel_launch(void* const* d_in, const int* in_sizes, int n_in,
                              void* d_out, int out_size)
{
    const float* hs   = (const float*)d_in[0];
    const float* cosp = (const float*)d_in[1];
    const float* sinp = (const float*)d_in[2];
    const float* wq   = (const float*)d_in[3];
    const float* wk   = (const float*)d_in[4];
    const float* wv   = (const float*)d_in[5];
    const float* wo   = (const float*)d_in[6];
    float* out = (float*)d_out;

    constexpr int SMEM_GEMM = 16384 * 4;   // 65536 B
    constexpr int SMEM_ATTN = 57344 * 4;   // 229376 B

    cudaFuncSetAttribute((const void*)gemm_tf32<0>,
                         cudaFuncAttributeMaxDynamicSharedMemorySize, SMEM_GEMM);
    cudaFuncSetAttribute((const void*)gemm_tf32<1>,
                         cudaFuncAttributeMaxDynamicSharedMemorySize, SMEM_GEMM);
    cudaFuncSetAttribute((const void*)attn_kernel,
                         cudaFuncAttributeMaxDynamicSharedMemorySize, SMEM_ATTN);

    gemm_tf32<0><<<dim3(48, 32), 256, SMEM_GEMM>>>(hs, wq, wk, wv, cosp, sinp, nullptr);
    attn_kernel<<<dim3(16, 32, 2), 256, SMEM_ATTN>>>();
    gemm_tf32<1><<<dim3(32, 32), 256, SMEM_GEMM>>>(nullptr, wo, nullptr, nullptr,
                                                   nullptr, nullptr, out);
}

// round 6
// speedup vs baseline: 1.4290x; 1.4290x over previous
#include <cuda_runtime.h>
#include <cstdint>

// Problem constants
constexpr int BATCH = 2, SEQ = 2048, DMODEL = 4096;
constexpr int NH = 32, NKV = 8, HD = 128;
constexpr int MROWS = BATCH * SEQ;                 // 4096
constexpr float ATT_SCALE = 0.08838834764831845f;  // 128^-0.5

// Scratch device globals (allocation-free per harness rules)
// k-dim of g_hs / g_w / g_wo / g_ao is stored PERMUTED within 8-groups:
// storage order per 8: k0,k4,k1,k5,k2,k6,k3,k7  (S[qperm(k)] = X[k])
__device__ float g_hs[(size_t)MROWS * DMODEL];
__device__ float g_w [(size_t)6144 * DMODEL];           // [wq;wk;wv]
__device__ float g_wo[(size_t)DMODEL * DMODEL];
// packed smem-image layouts for attention (round-2 format, proven):
__device__ float g_q [(size_t)BATCH * NH  * 16 * 16384];
__device__ float g_k [(size_t)BATCH * NKV * 32 * 8192];
__device__ float g_vt[(size_t)BATCH * NKV * 32 * 8192];
__device__ float g_ao[(size_t)MROWS * DMODEL];          // attention out (perm + tf32)

__device__ __forceinline__ float tf32r(float x) {
    uint32_t u;
    asm("cvt.rna.tf32.f32 %0, %1;" : "=r"(u) : "f"(x));
    return __uint_as_float(u);
}
__device__ __forceinline__ int qperm(int k) {
    return (k & ~7) | ((k & 3) << 1) | ((k >> 2) & 1);
}
__device__ __forceinline__ void mma8(float* c, const uint32_t* a, const uint32_t* b) {
    asm volatile(
        "mma.sync.aligned.m16n8k8.row.col.f32.tf32.tf32.f32 "
        "{%0,%1,%2,%3}, {%4,%5,%6,%7}, {%8,%9}, {%0,%1,%2,%3};"
        : "+f"(c[0]), "+f"(c[1]), "+f"(c[2]), "+f"(c[3])
        : "r"(a[0]), "r"(a[1]), "r"(a[2]), "r"(a[3]), "r"(b[0]), "r"(b[1]));
}
__device__ __forceinline__ void cpa16(float* s, const float* g) {
    uint32_t sa = (uint32_t)__cvta_generic_to_shared(s);
    asm volatile("cp.async.cg.shared.global [%0], [%1], 16;\n" :: "r"(sa), "l"(g));
}
#define CP_COMMIT() asm volatile("cp.async.commit_group;\n" ::: "memory")
#define CP_WAIT0()  asm volatile("cp.async.wait_group 0;\n" ::: "memory")
#define CP_WAIT2()  asm volatile("cp.async.wait_group 2;\n" ::: "memory")

// ---------------------------------------------------------------------------
// Pre-round to tf32 (RNA) + interleave k within 8-groups (two float4s ->
// two interleaved float4s; fully vectorized).
// ---------------------------------------------------------------------------
__global__ void preround(const float* __restrict__ hs, const float* __restrict__ wq,
                         const float* __restrict__ wk, const float* __restrict__ wv,
                         const float* __restrict__ wo)
{
    const size_t stride = (size_t)gridDim.x * blockDim.x;
    const size_t t0 = (size_t)blockIdx.x * blockDim.x + threadIdx.x;
    auto rnd = [&](const float* src, float* dst, size_t n8) {
        const float4* s = (const float4*)src;
        float4* d = (float4*)dst;
        for (size_t i = t0; i < n8; i += stride) {
            float4 a = s[2 * i], b = s[2 * i + 1];
            float4 o0 = make_float4(tf32r(a.x), tf32r(b.x), tf32r(a.y), tf32r(b.y));
            float4 o1 = make_float4(tf32r(a.z), tf32r(b.z), tf32r(a.w), tf32r(b.w));
            d[2 * i] = o0; d[2 * i + 1] = o1;
        }
    };
    rnd(hs, g_hs, (size_t)MROWS * DMODEL / 8);
    rnd(wq, g_w,                       (size_t)4096 * 4096 / 8);
    rnd(wk, g_w + (size_t)4096 * 4096, (size_t)1024 * 4096 / 8);
    rnd(wv, g_w + (size_t)5120 * 4096, (size_t)1024 * 4096 / 8);
    rnd(wo, g_wo, (size_t)4096 * 4096 / 8);
}

// ---------------------------------------------------------------------------
// mma.sync tf32 GEMM. BM=BN=128, BK=32, 256 thr / 8 warps (4m x 2n).
// Operands arrive pre-rounded & k-permuted -> cp.async direct to smem
// (stride 40 floats/row, conflict-free LDS.64 fragments). 4-stage pipeline.
// MODE 0: QKV + RoPE + packed-image scatter. MODE 1: out-proj -> Cout.
// ---------------------------------------------------------------------------
constexpr int RSTR = 40;                     // floats per smem row (160B)
constexpr int STAGE_F = 2 * 128 * RSTR;      // floats per stage (A+B) = 10240
template <int MODE>
__global__ void __launch_bounds__(256, 1)
gemm_tf32(const float* __restrict__ cosp, const float* __restrict__ sinp,
          float* __restrict__ Cout)
{
    extern __shared__ float smf[];
    const int tid = threadIdx.x, lane = tid & 31, wid = tid >> 5;
    const int gi = lane >> 2, ti = lane & 3;
    const int wm = wid >> 1, wn = wid & 1;
    const int bn = blockIdx.x, bm = blockIdx.y;
    const int m0 = bm * 128;
    const int nbase = bn * 128;

    const float* Ag = (MODE == 0) ? g_hs : g_ao;
    const float* Wg = (MODE == 0) ? g_w  : g_wo;

    const int r0 = tid >> 3, c0 = tid & 7;
    auto fill = [&](int t) {
        float* st = smf + (t & 3) * STAGE_F;
        const float* As = Ag + (size_t)(m0 + r0) * 4096 + t * 32 + c0 * 4;
        const float* Bs = Wg + (size_t)(nbase + r0) * 4096 + t * 32 + c0 * 4;
        float* sa = st + r0 * RSTR + c0 * 4;
        float* sb = st + 128 * RSTR + r0 * RSTR + c0 * 4;
#pragma unroll
        for (int i = 0; i < 4; i++) {
            cpa16(sa + 32 * i * RSTR, As + (size_t)32 * i * 4096);
            cpa16(sb + 32 * i * RSTR, Bs + (size_t)32 * i * 4096);
        }
    };

    float acc[2][8][4];
#pragma unroll
    for (int a = 0; a < 2; a++)
#pragma unroll
        for (int b2 = 0; b2 < 8; b2++)
#pragma unroll
            for (int c = 0; c < 4; c++) acc[a][b2][c] = 0.f;

    fill(0); CP_COMMIT();
    fill(1); CP_COMMIT();
    fill(2); CP_COMMIT();

    const int NK = 128;
    const int ra = wm * 32 + gi;
    const int nb = wn * 64 + gi;
    for (int kt = 0; kt < NK; kt++) {
        CP_WAIT2();
        __syncthreads();
        if (kt + 3 < NK) fill(kt + 3);
        CP_COMMIT();
        const float* Ab = smf + (kt & 3) * STAGE_F;
        const float* Bb = Ab + 128 * RSTR;
#pragma unroll
        for (int kg = 0; kg < 4; kg++) {
            const int kb = kg * 8 + ti * 2;
            uint32_t af[2][4];
#pragma unroll
            for (int mt = 0; mt < 2; mt++) {
                float2 a0 = *(const float2*)(Ab + (ra + mt * 16) * RSTR + kb);
                float2 a1 = *(const float2*)(Ab + (ra + mt * 16 + 8) * RSTR + kb);
                af[mt][0] = __float_as_uint(a0.x);
                af[mt][1] = __float_as_uint(a1.x);
                af[mt][2] = __float_as_uint(a0.y);
                af[mt][3] = __float_as_uint(a1.y);
            }
#pragma unroll
            for (int nt = 0; nt < 8; nt++) {
                float2 bv = *(const float2*)(Bb + (nb + nt * 8) * RSTR + kb);
                uint32_t bf[2] = { __float_as_uint(bv.x), __float_as_uint(bv.y) };
                mma8(acc[0][nt], af[0], bf);
                mma8(acc[1][nt], af[1], bf);
            }
        }
    }
    CP_WAIT0();
    __syncthreads();

    if (MODE == 1) {
#pragma unroll
        for (int mt = 0; mt < 2; mt++)
#pragma unroll
            for (int nt = 0; nt < 8; nt++) {
                int r = m0 + wm * 32 + mt * 16 + gi;
                int c = nbase + wn * 64 + nt * 8 + 2 * ti;
                *(float2*)(Cout + (size_t)r * 4096 + c) =
                    make_float2(acc[mt][nt][0], acc[mt][nt][1]);
                *(float2*)(Cout + (size_t)(r + 8) * 4096 + c) =
                    make_float2(acc[mt][nt][2], acc[mt][nt][3]);
            }
        return;
    }

    // MODE 0 epilogue: stage C tile in smem (stride 132), RoPE + packed scatter
    int btype, hidx;
    if (bn < 32)      { btype = 0; hidx = bn; }
    else if (bn < 40) { btype = 1; hidx = bn - 32; }
    else              { btype = 2; hidx = bn - 40; }

    float* Csh = smf; // 128*132 = 16896 floats, fits in stage memory
#pragma unroll
    for (int mt = 0; mt < 2; mt++)
#pragma unroll
        for (int nt = 0; nt < 8; nt++) {
            int r = wm * 32 + mt * 16 + gi, c = wn * 64 + nt * 8 + 2 * ti;
            Csh[r * 132 + c]           = acc[mt][nt][0];
            Csh[r * 132 + c + 1]       = acc[mt][nt][1];
            Csh[(r + 8) * 132 + c]     = acc[mt][nt][2];
            Csh[(r + 8) * 132 + c + 1] = acc[mt][nt][3];
        }
    __syncthreads();

    const int bb = m0 >> 11;
    if (btype <= 1) {
#pragma unroll 4
        for (int i = 0; i < 64; i++) {
            int f = tid + i * 256;
            int r = f >> 7, d = f & 127;
            int rx = (r & 3) << 3;
            int m = m0 + r, s = m & 2047;
            float val = Csh[r * 132 + d];
            float oth = Csh[r * 132 + ((d + 64) & 127)];
            float rot = (d < 64) ? -oth : oth;
            float cs = cosp[(size_t)m * HD + d];
            float sn = sinp[(size_t)m * HD + d];
            float ov = val * cs + rot * sn;
            if (btype == 0) {
                int qt = (m0 >> 7) & 15;
                size_t base = (((size_t)bb * NH + hidx) * 16 + qt) * 16384;
                g_q[base + r * 128 + (qperm(d) ^ rx)] = tf32r(ov * ATT_SCALE);
            } else {
                int kt = s >> 6, n = s & 63; // n&3 == r&3
                size_t base = (((size_t)bb * NKV + hidx) * 32 + kt) * 8192;
                g_k[base + n * 128 + (qperm(d) ^ rx)] = tf32r(ov);
            }
        }
    } else {
#pragma unroll 4
        for (int i = 0; i < 64; i++) {
            int f = tid + i * 256;
            int sl = f >> 7, d = f & 127;
            int s = (m0 & 2047) + sl;
            int kt = s >> 6;
            float v = Csh[sl * 132 + d];
            size_t base = (((size_t)bb * NKV + hidx) * 32 + kt) * 8192;
            g_vt[base + d * 64 + (qperm(sl & 63) ^ ((d & 3) << 3))] = tf32r(v);
        }
    }
}

// ---------------------------------------------------------------------------
// Flash attention (round-2, proven): packed images, cp.async double buffer.
// Output store adds k-permutation + tf32 rounding for the out-projection.
// ---------------------------------------------------------------------------
__global__ void __launch_bounds__(256, 1) attn_kernel()
{
    extern __shared__ float smf[];
    float* Qs  = smf;            // 16384
    float* Ksb = smf + 16384;    // 2 x 8192
    float* Vsb = smf + 32768;    // 2 x 8192
    float* Ps  = smf + 49152;    // 8192

    const int tid = threadIdx.x, lane = tid & 31, wid = tid >> 5;
    const int gi = lane >> 2, ti = lane & 3;
    const int qt = 15 - blockIdx.x;   // heaviest tiles first
    const int h = blockIdx.y, b = blockIdx.z;
    const int q0 = qt * 128, hk = h >> 2;
    const int sx = (gi & 3) << 3;

    const float* Qg = g_q + (((size_t)b * NH + h) * 16 + qt) * 16384;
    const float* Kg = g_k + ((size_t)b * NKV + hk) * 32 * 8192;
    const float* Vg = g_vt + ((size_t)b * NKV + hk) * 32 * 8192;

#pragma unroll
    for (int i = 0; i < 16; i++) { int x = (tid + i * 256) * 4; cpa16(Qs + x, Qg + x); }
#pragma unroll
    for (int i = 0; i < 8; i++)  { int x = (tid + i * 256) * 4; cpa16(Ksb + x, Kg + x); }
#pragma unroll
    for (int i = 0; i < 8; i++)  { int x = (tid + i * 256) * 4; cpa16(Vsb + x, Vg + x); }
    CP_COMMIT();

    float o[16][4];
#pragma unroll
    for (int a = 0; a < 16; a++)
#pragma unroll
        for (int c = 0; c < 4; c++) o[a][c] = 0.f;
    float mrow[2] = {-1e30f, -1e30f};
    float lrow[2] = {0.f, 0.f};

    const int r = wid * 16 + gi;
    const int nkt = 2 * qt + 2;
    for (int kt = 0; kt < nkt; kt++) {
        CP_WAIT0();
        __syncthreads();
        if (kt + 1 < nkt) {
            float* Kd = Ksb + ((kt + 1) & 1) * 8192;
            float* Vd = Vsb + ((kt + 1) & 1) * 8192;
            const float* Kg2 = Kg + (size_t)(kt + 1) * 8192;
            const float* Vg2 = Vg + (size_t)(kt + 1) * 8192;
#pragma unroll
            for (int i = 0; i < 8; i++) { int x = (tid + i * 256) * 4; cpa16(Kd + x, Kg2 + x); }
#pragma unroll
            for (int i = 0; i < 8; i++) { int x = (tid + i * 256) * 4; cpa16(Vd + x, Vg2 + x); }
            CP_COMMIT();
        }
        const float* Kb = Ksb + (kt & 1) * 8192;
        const float* Vb = Vsb + (kt & 1) * 8192;

        float sacc[8][4];
#pragma unroll
        for (int a = 0; a < 8; a++)
#pragma unroll
            for (int c = 0; c < 4; c++) sacc[a][c] = 0.f;
#pragma unroll 4
        for (int kg = 0; kg < 16; kg++) {
            const int kb = kg * 8 + ti * 2;
            float2 a0 = *(const float2*)(Qs + r * 128 + (kb ^ sx));
            float2 a1 = *(const float2*)(Qs + (r + 8) * 128 + (kb ^ sx));
            uint32_t af[4] = { __float_as_uint(a0.x), __float_as_uint(a1.x),
                               __float_as_uint(a0.y), __float_as_uint(a1.y) };
#pragma unroll
            for (int nt = 0; nt < 8; nt++) {
                int n = nt * 8 + gi;
                float2 bv = *(const float2*)(Kb + n * 128 + (kb ^ sx));
                uint32_t bf[2] = { __float_as_uint(bv.x), __float_as_uint(bv.y) };
                mma8(sacc[nt], af, bf);
            }
        }

        if (kt * 64 + 63 > q0 + wid * 16) {
#pragma unroll
            for (int nt = 0; nt < 8; nt++)
#pragma unroll
                for (int j = 0; j < 4; j++) {
                    int col = kt * 64 + nt * 8 + 2 * ti + (j & 1);
                    int row = q0 + wid * 16 + gi + (j >> 1) * 8;
                    if (col > row) sacc[nt][j] = -1e30f;
                }
        }

#pragma unroll
        for (int j = 0; j < 2; j++) {
            float mx = -1e30f;
#pragma unroll
            for (int nt = 0; nt < 8; nt++)
                mx = fmaxf(mx, fmaxf(sacc[nt][2 * j], sacc[nt][2 * j + 1]));
            mx = fmaxf(mx, __shfl_xor_sync(0xffffffffu, mx, 1));
            mx = fmaxf(mx, __shfl_xor_sync(0xffffffffu, mx, 2));
            float newm = fmaxf(mrow[j], mx);
            float alpha = __expf(mrow[j] - newm);
            mrow[j] = newm;
            float rs = 0.f;
#pragma unroll
            for (int nt = 0; nt < 8; nt++) {
                float p0 = __expf(sacc[nt][2 * j] - newm);
                float p1 = __expf(sacc[nt][2 * j + 1] - newm);
                sacc[nt][2 * j] = p0; sacc[nt][2 * j + 1] = p1;
                rs += p0 + p1;
            }
            rs += __shfl_xor_sync(0xffffffffu, rs, 1);
            rs += __shfl_xor_sync(0xffffffffu, rs, 2);
            lrow[j] = lrow[j] * alpha + rs;
#pragma unroll
            for (int nt = 0; nt < 16; nt++) {
                o[nt][2 * j] *= alpha; o[nt][2 * j + 1] *= alpha;
            }
            int row = wid * 16 + gi + j * 8;
#pragma unroll
            for (int nt = 0; nt < 8; nt++) {
                int c0 = nt * 8 + 2 * ti;
                Ps[row * 64 + (qperm(c0) ^ sx)]     = tf32r(sacc[nt][2 * j]);
                Ps[row * 64 + (qperm(c0 + 1) ^ sx)] = tf32r(sacc[nt][2 * j + 1]);
            }
        }
        __syncwarp();

#pragma unroll
        for (int kg = 0; kg < 8; kg++) {
            const int kb = kg * 8 + ti * 2;
            float2 a0 = *(const float2*)(Ps + r * 64 + (kb ^ sx));
            float2 a1 = *(const float2*)(Ps + (r + 8) * 64 + (kb ^ sx));
            uint32_t af[4] = { __float_as_uint(a0.x), __float_as_uint(a1.x),
                               __float_as_uint(a0.y), __float_as_uint(a1.y) };
#pragma unroll
            for (int nt = 0; nt < 16; nt++) {
                int n = nt * 8 + gi;
                float2 bv = *(const float2*)(Vb + n * 64 + (kb ^ sx));
                uint32_t bf[2] = { __float_as_uint(bv.x), __float_as_uint(bv.y) };
                mma8(o[nt], af, bf);
            }
        }
    }

    __syncthreads();
    const float inv0 = 1.f / lrow[0], inv1 = 1.f / lrow[1];
#pragma unroll
    for (int nt = 0; nt < 16; nt++) {
        int c = nt * 8 + 2 * ti;
        Qs[r * 128 + (c ^ sx)]             = o[nt][0] * inv0;
        Qs[r * 128 + ((c + 1) ^ sx)]       = o[nt][1] * inv0;
        Qs[(r + 8) * 128 + (c ^ sx)]       = o[nt][2] * inv1;
        Qs[(r + 8) * 128 + ((c + 1) ^ sx)] = o[nt][3] * inv1;
    }
    __syncthreads();
    // store k-PERMUTED (within head's 8-groups) + tf32-rounded for out-proj
    float* AOg = g_ao + ((size_t)(b * SEQ + q0)) * DMODEL + h * HD;
#pragma unroll 4
    for (int i = 0; i < 64; i++) {
        int f = tid + i * 256;
        int rr = f >> 7, d = f & 127;
        AOg[(size_t)rr * DMODEL + qperm(d)] =
            tf32r(Qs[rr * 128 + (d ^ ((rr & 3) << 3))]);
    }
}

// ---------------------------------------------------------------------------
extern "C" void kernel_launch(void* const* d_in, const int* in_sizes, int n_in,
                              void* d_out, int out_size)
{
    const float* hs   = (const float*)d_in[0];
    const float* cosp = (const float*)d_in[1];
    const float* sinp = (const float*)d_in[2];
    const float* wq   = (const float*)d_in[3];
    const float* wk   = (const float*)d_in[4];
    const float* wv   = (const float*)d_in[5];
    const float* wo   = (const float*)d_in[6];
    float* out = (float*)d_out;

    constexpr int SMEM_GEMM = 4 * STAGE_F * 4;    // 4 stages * 40960 B = 163840
    constexpr int SMEM_ATTN = 57344 * 4;          // 229376 B

    cudaFuncSetAttribute((const void*)gemm_tf32<0>,
                         cudaFuncAttributeMaxDynamicSharedMemorySize, SMEM_GEMM);
    cudaFuncSetAttribute((const void*)gemm_tf32<1>,
                         cudaFuncAttributeMaxDynamicSharedMemorySize, SMEM_GEMM);
    cudaFuncSetAttribute((const void*)attn_kernel,
                         cudaFuncAttributeMaxDynamicSharedMemorySize, SMEM_ATTN);

    preround<<<1184, 256>>>(hs, wq, wk, wv, wo);
    gemm_tf32<0><<<dim3(48, 32), 256, SMEM_GEMM>>>(cosp, sinp, nullptr);
    attn_kernel<<<dim3(16, 32, 2), 256, SMEM_ATTN>>>();
    gemm_tf32<1><<<dim3(32, 32), 256, SMEM_GEMM>>>(nullptr, nullptr, out);
}

// round 10
// speedup vs baseline: 1.4486x; 1.0137x over previous
#include <cuda_runtime.h>
#include <cstdint>

// Problem constants
constexpr int BATCH = 2, SEQ = 2048, DMODEL = 4096;
constexpr int NH = 32, NKV = 8, HD = 128;
constexpr int MROWS = BATCH * SEQ;                 // 4096
constexpr float ATT_SCALE = 0.08838834764831845f;  // 128^-0.5

// Scratch device globals. k-dim of g_hs/g_w/g_wo/g_ao stored PERMUTED within
// 8-groups: order k0,k4,k1,k5,k2,k6,k3,k7 (S[qperm(k)] = X[k]).
__device__ float g_hs[(size_t)MROWS * DMODEL];
__device__ float g_w [(size_t)6144 * DMODEL];           // [wq;wk;wv]
__device__ float g_wo[(size_t)DMODEL * DMODEL];
// packed smem-image layouts for attention (proven):
__device__ float g_q [(size_t)BATCH * NH  * 16 * 16384];
__device__ float g_k [(size_t)BATCH * NKV * 32 * 8192];
__device__ float g_vt[(size_t)BATCH * NKV * 32 * 8192];
__device__ float g_ao[(size_t)MROWS * DMODEL];          // attention out (perm + tf32)

__device__ __forceinline__ float tf32r(float x) {
    uint32_t u;
    asm("cvt.rna.tf32.f32 %0, %1;" : "=r"(u) : "f"(x));
    return __uint_as_float(u);
}
__device__ __forceinline__ int qperm(int k) {
    return (k & ~7) | ((k & 3) << 1) | ((k >> 2) & 1);
}
__device__ __forceinline__ void mma8(float* c, const uint32_t* a, const uint32_t* b) {
    asm volatile(
        "mma.sync.aligned.m16n8k8.row.col.f32.tf32.tf32.f32 "
        "{%0,%1,%2,%3}, {%4,%5,%6,%7}, {%8,%9}, {%0,%1,%2,%3};"
        : "+f"(c[0]), "+f"(c[1]), "+f"(c[2]), "+f"(c[3])
        : "r"(a[0]), "r"(a[1]), "r"(a[2]), "r"(a[3]), "r"(b[0]), "r"(b[1]));
}
__device__ __forceinline__ void cpa16(float* s, const float* g) {
    uint32_t sa = (uint32_t)__cvta_generic_to_shared(s);
    asm volatile("cp.async.cg.shared.global [%0], [%1], 16;\n" :: "r"(sa), "l"(g));
}
#define CP_COMMIT() asm volatile("cp.async.commit_group;\n" ::: "memory")
#define CP_WAIT0()  asm volatile("cp.async.wait_group 0;\n" ::: "memory")
#define CP_WAIT1()  asm volatile("cp.async.wait_group 1;\n" ::: "memory")

// ---------------------------------------------------------------------------
// Pre-round to tf32 (RNA) + interleave k within 8-groups (vectorized shuffle).
// ---------------------------------------------------------------------------
__global__ void preround(const float* __restrict__ hs, const float* __restrict__ wq,
                         const float* __restrict__ wk, const float* __restrict__ wv,
                         const float* __restrict__ wo)
{
    const size_t stride = (size_t)gridDim.x * blockDim.x;
    const size_t t0 = (size_t)blockIdx.x * blockDim.x + threadIdx.x;
    auto rnd = [&](const float* src, float* dst, size_t n8) {
        const float4* s = (const float4*)src;
        float4* d = (float4*)dst;
        for (size_t i = t0; i < n8; i += stride) {
            float4 a = s[2 * i], b = s[2 * i + 1];
            float4 o0 = make_float4(tf32r(a.x), tf32r(b.x), tf32r(a.y), tf32r(b.y));
            float4 o1 = make_float4(tf32r(a.z), tf32r(b.z), tf32r(a.w), tf32r(b.w));
            d[2 * i] = o0; d[2 * i + 1] = o1;
        }
    };
    rnd(hs, g_hs, (size_t)MROWS * DMODEL / 8);
    rnd(wq, g_w,                       (size_t)4096 * 4096 / 8);
    rnd(wk, g_w + (size_t)4096 * 4096, (size_t)1024 * 4096 / 8);
    rnd(wv, g_w + (size_t)5120 * 4096, (size_t)1024 * 4096 / 8);
    rnd(wo, g_wo, (size_t)4096 * 4096 / 8);
}

// ---------------------------------------------------------------------------
// mma.sync tf32 GEMM. BM=128, BN=256, BK=32. 256 thr / 8 warps (2m x 4n),
// warp tile 64x64 (0.5 LDS.64 per MMA). 3-stage cp.async pipeline.
// MODE 0: QKV + RoPE + packed-image scatter (2 heads per bn).
// MODE 1: out-proj -> Cout.
// ---------------------------------------------------------------------------
constexpr int RSTR = 40;                      // floats per smem row (160B)
constexpr int STAGE_F = (128 + 256) * RSTR;   // 15360 floats per stage
template <int MODE>
__global__ void __launch_bounds__(256, 1)
gemm_tf32(const float* __restrict__ cosp, const float* __restrict__ sinp,
          float* __restrict__ Cout)
{
    extern __shared__ float smf[];
    const int tid = threadIdx.x, lane = tid & 31, wid = tid >> 5;
    const int gi = lane >> 2, ti = lane & 3;
    const int wm = wid >> 2, wn = wid & 3;
    const int bn = blockIdx.x, bm = blockIdx.y;
    const int m0 = bm * 128;
    const int nbase = bn * 256;

    const float* Ag = (MODE == 0) ? g_hs : g_ao;
    const float* Wg = (MODE == 0) ? g_w  : g_wo;

    const int r0 = tid >> 3, c0 = tid & 7;
    auto fill = [&](int t, int buf) {
        float* st = smf + buf * STAGE_F;
        const float* As = Ag + (size_t)(m0 + r0) * 4096 + t * 32 + c0 * 4;
        const float* Bs = Wg + (size_t)(nbase + r0) * 4096 + t * 32 + c0 * 4;
        float* sa = st + r0 * RSTR + c0 * 4;
        float* sb = st + 128 * RSTR + r0 * RSTR + c0 * 4;
#pragma unroll
        for (int i = 0; i < 4; i++)
            cpa16(sa + 32 * i * RSTR, As + (size_t)32 * i * 4096);
#pragma unroll
        for (int i = 0; i < 8; i++)
            cpa16(sb + 32 * i * RSTR, Bs + (size_t)32 * i * 4096);
    };

    float acc[4][8][4];
#pragma unroll
    for (int a = 0; a < 4; a++)
#pragma unroll
        for (int b2 = 0; b2 < 8; b2++)
#pragma unroll
            for (int c = 0; c < 4; c++) acc[a][b2][c] = 0.f;

    fill(0, 0); CP_COMMIT();
    fill(1, 1); CP_COMMIT();

    const int NK = 128;
    const int ra = wm * 64 + gi;
    const int nb = wn * 64 + gi;
    int buf = 0;
    for (int kt = 0; kt < NK; kt++) {
        CP_WAIT1();
        __syncthreads();
        if (kt + 2 < NK) {
            int nbuf = buf + 2; if (nbuf >= 3) nbuf -= 3;
            fill(kt + 2, nbuf);
        }
        CP_COMMIT();
        const float* Ab = smf + buf * STAGE_F;
        const float* Bb = Ab + 128 * RSTR;
#pragma unroll
        for (int kg = 0; kg < 4; kg++) {
            const int kb = kg * 8 + ti * 2;
            uint32_t af[4][4];
#pragma unroll
            for (int mt = 0; mt < 4; mt++) {
                float2 a0 = *(const float2*)(Ab + (ra + mt * 16) * RSTR + kb);
                float2 a1 = *(const float2*)(Ab + (ra + mt * 16 + 8) * RSTR + kb);
                af[mt][0] = __float_as_uint(a0.x);
                af[mt][1] = __float_as_uint(a1.x);
                af[mt][2] = __float_as_uint(a0.y);
                af[mt][3] = __float_as_uint(a1.y);
            }
#pragma unroll
            for (int nt = 0; nt < 8; nt++) {
                float2 bv = *(const float2*)(Bb + (nb + nt * 8) * RSTR + kb);
                uint32_t bf[2] = { __float_as_uint(bv.x), __float_as_uint(bv.y) };
#pragma unroll
                for (int mt = 0; mt < 4; mt++)
                    mma8(acc[mt][nt], af[mt], bf);
            }
        }
        if (++buf == 3) buf = 0;
    }
    CP_WAIT0();
    __syncthreads();

    if (MODE == 1) {
#pragma unroll
        for (int mt = 0; mt < 4; mt++)
#pragma unroll
            for (int nt = 0; nt < 8; nt++) {
                int r = m0 + wm * 64 + mt * 16 + gi;
                int c = nbase + wn * 64 + nt * 8 + 2 * ti;
                *(float2*)(Cout + (size_t)r * 4096 + c) =
                    make_float2(acc[mt][nt][0], acc[mt][nt][1]);
                *(float2*)(Cout + (size_t)(r + 8) * 4096 + c) =
                    make_float2(acc[mt][nt][2], acc[mt][nt][3]);
            }
        return;
    }

    // MODE 0 epilogue: stage C tile (128 x 264), then RoPE / scatter (2 heads)
    int btype, h2;                  // h2 = first head of the pair
    if (bn < 16)      { btype = 0; h2 = 2 * bn; }
    else if (bn < 20) { btype = 1; h2 = 2 * (bn - 16); }
    else              { btype = 2; h2 = 2 * (bn - 20); }

    float* Csh = smf;               // 128*264 = 33792 floats (fits in stages)
#pragma unroll
    for (int mt = 0; mt < 4; mt++)
#pragma unroll
        for (int nt = 0; nt < 8; nt++) {
            int r = wm * 64 + mt * 16 + gi, c = wn * 64 + nt * 8 + 2 * ti;
            Csh[r * 264 + c]           = acc[mt][nt][0];
            Csh[r * 264 + c + 1]       = acc[mt][nt][1];
            Csh[(r + 8) * 264 + c]     = acc[mt][nt][2];
            Csh[(r + 8) * 264 + c + 1] = acc[mt][nt][3];
        }
    __syncthreads();

    const int bb = m0 >> 11;
    if (btype <= 1) {
#pragma unroll 4
        for (int i = 0; i < 128; i++) {
            int f = tid + i * 256;
            int r = f >> 8, c = f & 255;
            int hh = c >> 7, d = c & 127;
            int rx = (r & 3) << 3;
            int m = m0 + r, s = m & 2047;
            float val = Csh[r * 264 + c];
            float oth = Csh[r * 264 + hh * 128 + ((d + 64) & 127)];
            float rot = (d < 64) ? -oth : oth;
            float cs = cosp[(size_t)m * HD + d];
            float sn = sinp[(size_t)m * HD + d];
            float ov = val * cs + rot * sn;
            if (btype == 0) {
                int qt = (m0 >> 7) & 15;
                size_t base = (((size_t)bb * NH + (h2 + hh)) * 16 + qt) * 16384;
                g_q[base + r * 128 + (qperm(d) ^ rx)] = tf32r(ov * ATT_SCALE);
            } else {
                int kt = s >> 6, n = s & 63; // n&3 == r&3
                size_t base = (((size_t)bb * NKV + (h2 + hh)) * 32 + kt) * 8192;
                g_k[base + n * 128 + (qperm(d) ^ rx)] = tf32r(ov);
            }
        }
    } else {
#pragma unroll 4
        for (int i = 0; i < 128; i++) {
            int f = tid + i * 256;
            int sl = f >> 8, c = f & 255;
            int hh = c >> 7, d = c & 127;
            int s = (m0 & 2047) + sl;
            int kt = s >> 6;
            float v = Csh[sl * 264 + c];
            size_t base = (((size_t)bb * NKV + (h2 + hh)) * 32 + kt) * 8192;
            g_vt[base + d * 64 + (qperm(sl & 63) ^ ((d & 3) << 3))] = tf32r(v);
        }
    }
}

// ---------------------------------------------------------------------------
// Flash attention (proven): packed images, cp.async double buffer.
// Output store: k-permuted + tf32-rounded for the out-projection.
// ---------------------------------------------------------------------------
__global__ void __launch_bounds__(256, 1) attn_kernel()
{
    extern __shared__ float smf[];
    float* Qs  = smf;            // 16384
    float* Ksb = smf + 16384;    // 2 x 8192
    float* Vsb = smf + 32768;    // 2 x 8192
    float* Ps  = smf + 49152;    // 8192

    const int tid = threadIdx.x, lane = tid & 31, wid = tid >> 5;
    const int gi = lane >> 2, ti = lane & 3;
    const int qt = 15 - blockIdx.x;   // heaviest tiles first
    const int h = blockIdx.y, b = blockIdx.z;
    const int q0 = qt * 128, hk = h >> 2;
    const int sx = (gi & 3) << 3;

    const float* Qg = g_q + (((size_t)b * NH + h) * 16 + qt) * 16384;
    const float* Kg = g_k + ((size_t)b * NKV + hk) * 32 * 8192;
    const float* Vg = g_vt + ((size_t)b * NKV + hk) * 32 * 8192;

#pragma unroll
    for (int i = 0; i < 16; i++) { int x = (tid + i * 256) * 4; cpa16(Qs + x, Qg + x); }
#pragma unroll
    for (int i = 0; i < 8; i++)  { int x = (tid + i * 256) * 4; cpa16(Ksb + x, Kg + x); }
#pragma unroll
    for (int i = 0; i < 8; i++)  { int x = (tid + i * 256) * 4; cpa16(Vsb + x, Vg + x); }
    CP_COMMIT();

    float o[16][4];
#pragma unroll
    for (int a = 0; a < 16; a++)
#pragma unroll
        for (int c = 0; c < 4; c++) o[a][c] = 0.f;
    float mrow[2] = {-1e30f, -1e30f};
    float lrow[2] = {0.f, 0.f};

    const int r = wid * 16 + gi;
    const int nkt = 2 * qt + 2;
    for (int kt = 0; kt < nkt; kt++) {
        CP_WAIT0();
        __syncthreads();
        if (kt + 1 < nkt) {
            float* Kd = Ksb + ((kt + 1) & 1) * 8192;
            float* Vd = Vsb + ((kt + 1) & 1) * 8192;
            const float* Kg2 = Kg + (size_t)(kt + 1) * 8192;
            const float* Vg2 = Vg + (size_t)(kt + 1) * 8192;
#pragma unroll
            for (int i = 0; i < 8; i++) { int x = (tid + i * 256) * 4; cpa16(Kd + x, Kg2 + x); }
#pragma unroll
            for (int i = 0; i < 8; i++) { int x = (tid + i * 256) * 4; cpa16(Vd + x, Vg2 + x); }
            CP_COMMIT();
        }
        const float* Kb = Ksb + (kt & 1) * 8192;
        const float* Vb = Vsb + (kt & 1) * 8192;

        float sacc[8][4];
#pragma unroll
        for (int a = 0; a < 8; a++)
#pragma unroll
            for (int c = 0; c < 4; c++) sacc[a][c] = 0.f;
#pragma unroll 4
        for (int kg = 0; kg < 16; kg++) {
            const int kb = kg * 8 + ti * 2;
            float2 a0 = *(const float2*)(Qs + r * 128 + (kb ^ sx));
            float2 a1 = *(const float2*)(Qs + (r + 8) * 128 + (kb ^ sx));
            uint32_t af[4] = { __float_as_uint(a0.x), __float_as_uint(a1.x),
                               __float_as_uint(a0.y), __float_as_uint(a1.y) };
#pragma unroll
            for (int nt = 0; nt < 8; nt++) {
                int n = nt * 8 + gi;
                float2 bv = *(const float2*)(Kb + n * 128 + (kb ^ sx));
                uint32_t bf[2] = { __float_as_uint(bv.x), __float_as_uint(bv.y) };
                mma8(sacc[nt], af, bf);
            }
        }

        if (kt * 64 + 63 > q0 + wid * 16) {
#pragma unroll
            for (int nt = 0; nt < 8; nt++)
#pragma unroll
                for (int j = 0; j < 4; j++) {
                    int col = kt * 64 + nt * 8 + 2 * ti + (j & 1);
                    int row = q0 + wid * 16 + gi + (j >> 1) * 8;
                    if (col > row) sacc[nt][j] = -1e30f;
                }
        }

#pragma unroll
        for (int j = 0; j < 2; j++) {
            float mx = -1e30f;
#pragma unroll
            for (int nt = 0; nt < 8; nt++)
                mx = fmaxf(mx, fmaxf(sacc[nt][2 * j], sacc[nt][2 * j + 1]));
            mx = fmaxf(mx, __shfl_xor_sync(0xffffffffu, mx, 1));
            mx = fmaxf(mx, __shfl_xor_sync(0xffffffffu, mx, 2));
            float newm = fmaxf(mrow[j], mx);
            float alpha = __expf(mrow[j] - newm);
            mrow[j] = newm;
            float rs = 0.f;
#pragma unroll
            for (int nt = 0; nt < 8; nt++) {
                float p0 = __expf(sacc[nt][2 * j] - newm);
                float p1 = __expf(sacc[nt][2 * j + 1] - newm);
                sacc[nt][2 * j] = p0; sacc[nt][2 * j + 1] = p1;
                rs += p0 + p1;
            }
            rs += __shfl_xor_sync(0xffffffffu, rs, 1);
            rs += __shfl_xor_sync(0xffffffffu, rs, 2);
            lrow[j] = lrow[j] * alpha + rs;
#pragma unroll
            for (int nt = 0; nt < 16; nt++) {
                o[nt][2 * j] *= alpha; o[nt][2 * j + 1] *= alpha;
            }
            int row = wid * 16 + gi + j * 8;
#pragma unroll
            for (int nt = 0; nt < 8; nt++) {
                int c0 = nt * 8 + 2 * ti;
                Ps[row * 64 + (qperm(c0) ^ sx)]     = tf32r(sacc[nt][2 * j]);
                Ps[row * 64 + (qperm(c0 + 1) ^ sx)] = tf32r(sacc[nt][2 * j + 1]);
            }
        }
        __syncwarp();

#pragma unroll
        for (int kg = 0; kg < 8; kg++) {
            const int kb = kg * 8 + ti * 2;
            float2 a0 = *(const float2*)(Ps + r * 64 + (kb ^ sx));
            float2 a1 = *(const float2*)(Ps + (r + 8) * 64 + (kb ^ sx));
            uint32_t af[4] = { __float_as_uint(a0.x), __float_as_uint(a1.x),
                               __float_as_uint(a0.y), __float_as_uint(a1.y) };
#pragma unroll
            for (int nt = 0; nt < 16; nt++) {
                int n = nt * 8 + gi;
                float2 bv = *(const float2*)(Vb + n * 64 + (kb ^ sx));
                uint32_t bf[2] = { __float_as_uint(bv.x), __float_as_uint(bv.y) };
                mma8(o[nt], af, bf);
            }
        }
    }

    __syncthreads();
    const float inv0 = 1.f / lrow[0], inv1 = 1.f / lrow[1];
#pragma unroll
    for (int nt = 0; nt < 16; nt++) {
        int c = nt * 8 + 2 * ti;
        Qs[r * 128 + (c ^ sx)]             = o[nt][0] * inv0;
        Qs[r * 128 + ((c + 1) ^ sx)]       = o[nt][1] * inv0;
        Qs[(r + 8) * 128 + (c ^ sx)]       = o[nt][2] * inv1;
        Qs[(r + 8) * 128 + ((c + 1) ^ sx)] = o[nt][3] * inv1;
    }
    __syncthreads();
    float* AOg = g_ao + ((size_t)(b * SEQ + q0)) * DMODEL + h * HD;
#pragma unroll 4
    for (int i = 0; i < 64; i++) {
        int f = tid + i * 256;
        int rr = f >> 7, d = f & 127;
        AOg[(size_t)rr * DMODEL + qperm(d)] =
            tf32r(Qs[rr * 128 + (d ^ ((rr & 3) << 3))]);
    }
}

// ---------------------------------------------------------------------------
extern "C" void kernel_launch(void* const* d_in, const int* in_sizes, int n_in,
                              void* d_out, int out_size)
{
    const float* hs   = (const float*)d_in[0];
    const float* cosp = (const float*)d_in[1];
    const float* sinp = (const float*)d_in[2];
    const float* wq   = (const float*)d_in[3];
    const float* wk   = (const float*)d_in[4];
    const float* wv   = (const float*)d_in[5];
    const float* wo   = (const float*)d_in[6];
    float* out = (float*)d_out;

    constexpr int SMEM_GEMM = 3 * STAGE_F * 4;    // 184320 B
    constexpr int SMEM_ATTN = 57344 * 4;          // 229376 B

    cudaFuncSetAttribute((const void*)gemm_tf32<0>,
                         cudaFuncAttributeMaxDynamicSharedMemorySize, SMEM_GEMM);
    cudaFuncSetAttribute((const void*)gemm_tf32<1>,
                         cudaFuncAttributeMaxDynamicSharedMemorySize, SMEM_GEMM);
    cudaFuncSetAttribute((const void*)attn_kernel,
                         cudaFuncAttributeMaxDynamicSharedMemorySize, SMEM_ATTN);

    preround<<<1184, 256>>>(hs, wq, wk, wv, wo);
    gemm_tf32<0><<<dim3(24, 32), 256, SMEM_GEMM>>>(cosp, sinp, nullptr);
    attn_kernel<<<dim3(16, 32, 2), 256, SMEM_ATTN>>>();
    gemm_tf32<1><<<dim3(16, 32), 256, SMEM_GEMM>>>(nullptr, nullptr, out);
}